// round 15
// baseline (speedup 1.0000x reference)
#include <cuda_runtime.h>
#include <cuda_fp16.h>
#include <cstdint>
#include <math.h>

// ---------------- problem constants ----------------
#define BATCH 4096
#define LSEQ  28
#define VOCAB 32000
#define DIM   300
#define BW_E  8704            // per-batch row: 300 front pad + 8400 data + 4 back pad
#define KPAD_F 128
#define K1    1504            // conv1/conv2 GEMM K (1500 padded)
#define K3    3008            // conv3 GEMM K (3000 padded)
#define BW_H1 3904            // 13*300 + 4
#define BW_H2 3008            // 5*600 + 8
#define L1o   13
#define C1    300
#define L2o   5
#define C2    600
#define C3    100
#define M1    (BATCH*L1o)     // 53248 = 416*128
#define M2    (BATCH*L2o)     // 20480 = 160*128
#define NPAIRS 8386560
#define HOUT  (BATCH*C3)

// ---------------- scratch (lo-buffers kept ONLY where actually read) ----------------
__device__ __half g_Eh[(size_t)BATCH*BW_E + 64];
__device__ __half g_W1h[384*K1];
__device__ __half g_W2h[640*K1];
__device__ __half g_W3h[128*K3], g_W3l[128*K3];
__device__ float g_h1[(size_t)M1*C1];
__device__ float g_h2[(size_t)M2*C2];
__device__ __half g_h1h[(size_t)BATCH*BW_H1 + 64];
__device__ __half g_h2h[(size_t)BATCH*BW_H2 + 64], g_h2l[(size_t)BATCH*BW_H2 + 64];
__device__ float g_final[BATCH*C3];
__device__ __half g_Fnh[BATCH*KPAD_F], g_Fnl[BATCH*KPAD_F];
__device__ float g_mean1[C1], g_istd1[C1];
__device__ float g_mean2[C2], g_istd2[C2];
__device__ float g_part[32*640*2];

// ---------------- gather + fused renorm into position-major E_T (hi only) ----------------
__global__ __launch_bounds__(256)
void k_gather(const int* __restrict__ x, const float* __restrict__ emb) {
    __shared__ float sx[LSEQ * DIM];     // 33.6 KB
    __shared__ int   tok[LSEQ];
    __shared__ float nrm[LSEQ];
    int b = blockIdx.x, t = threadIdx.x;
    int lane = t & 31, wid = t >> 5;
    bool is64 = (x[1] == 0 && x[3] == 0 && x[5] == 0 && x[7] == 0);
    if (t < LSEQ) {
        tok[t] = is64 ? x[(b * LSEQ + t) * 2] : x[b * LSEQ + t];
    }
    __syncthreads();
    // stage token rows in smem (coalesced per row)
    #pragma unroll
    for (int l = 0; l < LSEQ; l++) {
        const float* row = emb + (size_t)tok[l] * DIM;
        for (int ci = t; ci < DIM; ci += 256) sx[l * DIM + ci] = row[ci];
    }
    __syncthreads();
    // norms: warp w handles tokens l = w, w+8, ... ; summation order identical to old k_scales
    for (int l = wid; l < LSEQ; l += 8) {
        float s = 0.f;
        for (int d = lane; d < DIM; d += 32) { float v = sx[l * DIM + d]; s += v * v; }
        #pragma unroll
        for (int o = 16; o; o >>= 1) s += __shfl_xor_sync(0xffffffffu, s, o);
        if (lane == 0) nrm[l] = fminf(1.f, 1.f / (sqrtf(s) + 1e-7f));
    }
    __syncthreads();
    __half* dH = g_Eh + (size_t)b * BW_E;
    const __half z = __float2half_rn(0.f);
    for (int i = t; i < 304; i += 256) {
        int o = (i < 300) ? i : (8400 + i);
        dH[o] = z;
    }
    #pragma unroll
    for (int l = 0; l < LSEQ; l++) {
        float sc = nrm[l];
        for (int ci = t; ci < DIM; ci += 256)
            dH[300 + l * DIM + ci] = __float2half_rn(sx[l * DIM + ci] * sc);
    }
}

// ---------------- weight prep (w1/w2 hi only; w3 split) ----------------
__global__ void k_prep_w(const float* __restrict__ w1, const float* __restrict__ w2,
                         const float* __restrict__ w3) {
    const int n1 = 384 * K1, n2 = 640 * K1, n3 = 128 * K3;
    int total = n1 + n2 + n3;
    for (int idx = blockIdx.x * blockDim.x + threadIdx.x; idx < total; idx += gridDim.x * blockDim.x) {
        int i = idx;
        if (i < n1) {
            int n = i / K1, k = i - n * K1;
            int kk = k / 300, ci = k - kk * 300;
            float v = (n < C1 && kk < 5) ? w1[n * 1500 + ci * 5 + kk] : 0.f;
            g_W1h[i] = __float2half_rn(v);
            continue;
        }
        i -= n1;
        if (i < n2) {
            int n = i / K1, k = i - n * K1;
            int kk = k / 300, ci = k - kk * 300;
            float v = (n < C2 && kk < 5) ? w2[n * 1500 + ci * 5 + kk] : 0.f;
            g_W2h[i] = __float2half_rn(v);
            continue;
        }
        i -= n2;
        {
            int n = i / K3, k = i - n * K3;
            int kk = k / 600, ci = k - kk * 600;
            float v = (n < C3 && kk < 5) ? w3[n * 3000 + ci * 5 + kk] : 0.f;
            __half h = __float2half_rn(v);
            g_W3h[i] = h;
            g_W3l[i] = __float2half_rn(v - __half2float(h));
        }
    }
}

// ---------------- zero tail pads ----------------
__global__ void k_padzero() {
    int b = blockIdx.x * blockDim.x + threadIdx.x;
    const __half z = __float2half_rn(0.f);
    if (b < BATCH) {
        #pragma unroll
        for (int i = 0; i < 4; i++) {
            g_h1h[(size_t)b * BW_H1 + 3900 + i] = z;
        }
        #pragma unroll
        for (int i = 0; i < 8; i++) {
            g_h2h[(size_t)b * BW_H2 + 3000 + i] = z;
            g_h2l[(size_t)b * BW_H2 + 3000 + i] = z;
        }
    }
    if (b < 64) {
        g_Eh[(size_t)BATCH * BW_E + b]   = z;
        g_h1h[(size_t)BATCH * BW_H1 + b] = z;
        g_h2h[(size_t)BATCH * BW_H2 + b] = z;
        g_h2l[(size_t)BATCH * BW_H2 + b] = z;
    }
}

// ---------------- BN stats ----------------
__global__ void k_bnstat_p(const float* __restrict__ h, int M, int C) {
    int lane = threadIdx.x & 31;
    int w = threadIdx.x >> 5;
    int c = blockIdx.x * 32 + lane;
    int chunk = blockIdx.y;
    int rpc = M >> 5;
    float s = 0.f, s2 = 0.f;
    if (c < C) {
        int r1 = (chunk + 1) * rpc;
        for (int r = chunk * rpc + w; r < r1; r += 8) {
            float v = h[(size_t)r * C + c];
            s += v; s2 += v * v;
        }
    }
    __shared__ float sh[8][32][2];
    sh[w][lane][0] = s; sh[w][lane][1] = s2;
    __syncthreads();
    if (threadIdx.x < 32) {
        float S = 0.f, S2 = 0.f;
        #pragma unroll
        for (int i = 0; i < 8; i++) { S += sh[i][threadIdx.x][0]; S2 += sh[i][threadIdx.x][1]; }
        int cc = blockIdx.x * 32 + threadIdx.x;
        if (cc < C) {
            g_part[(chunk * 640 + cc) * 2 + 0] = S;
            g_part[(chunk * 640 + cc) * 2 + 1] = S2;
        }
    }
}

__global__ void k_bnstat_r(int C, float invN, float* __restrict__ mean, float* __restrict__ istd) {
    int c = blockIdx.x * blockDim.x + threadIdx.x;
    if (c >= C) return;
    float S = 0.f, S2 = 0.f;
    for (int ch = 0; ch < 32; ch++) {
        S  += g_part[(ch * 640 + c) * 2 + 0];
        S2 += g_part[(ch * 640 + c) * 2 + 1];
    }
    float m = S * invN;
    mean[c] = m;
    istd[c] = rsqrtf(S2 * invN - m * m + 1e-5f);
}

// ---------------- BN apply + ReLU + fp16 (optionally split) into padded T layout ----------------
__global__ void k_bnapply(const float* __restrict__ h, __half* __restrict__ oh,
                          __half* __restrict__ ol,
                          const float* __restrict__ mean, const float* __restrict__ istd,
                          const float* __restrict__ gamma, const float* __restrict__ beta,
                          int M, int C, int lout, int pad) {
    size_t total = (size_t)M * C;
    size_t stride = (size_t)gridDim.x * blockDim.x;
    for (size_t idx = (size_t)blockIdx.x * blockDim.x + threadIdx.x; idx < total; idx += stride) {
        int m = (int)(idx / C), c = (int)(idx - (size_t)m * C);
        float v = (h[idx] - mean[c]) * istd[c] * gamma[c] + beta[c];
        v = fmaxf(v, 0.f);
        size_t off = idx + (size_t)pad * (m / lout);
        __half hi = __float2half_rn(v);
        oh[off] = hi;
        if (ol) ol[off] = __float2half_rn(v - __half2float(hi));
    }
}

// ---------------- row-normalize final -> fp16 hi/lo ----------------
__global__ void k_norm() {
    int gw = (blockIdx.x * blockDim.x + threadIdx.x) >> 5;
    int lane = threadIdx.x & 31;
    if (gw >= BATCH) return;
    const float* f = g_final + gw * C3;
    float s = 0.f;
    for (int c = lane; c < C3; c += 32) { float v = f[c]; s += v * v; }
    #pragma unroll
    for (int o = 16; o; o >>= 1) s += __shfl_xor_sync(0xffffffffu, s, o);
    float n = sqrtf(s);
    __half* oh = g_Fnh + gw * KPAD_F;
    __half* ol = g_Fnl + gw * KPAD_F;
    for (int c = lane; c < C3; c += 32) {
        float v = f[c] / n;
        __half h = __float2half_rn(v);
        oh[c] = h;
        ol[c] = __float2half_rn(v - __half2float(h));
    }
    for (int c = C3 + lane; c < KPAD_F; c += 32) {
        oh[c] = __float2half_rn(0.f);
        ol[c] = __float2half_rn(0.f);
    }
}

// ================= HMMA GEMM machinery (split-fp16, swizzled smem) =================
// CTA 128x128, 128 threads = 4 warps of 64x64. STAGES-deep cp.async pipeline, Kc=32.
// TERMS=3: C = Ah*Bh + Ah*Bl + Al*Bh ; TERMS=2: + Ah*Bl ; TERMS=1: Ah*Bh only
#define GBM 128
#define GBK 32
#define MSZ (128*32)

__device__ __forceinline__ void cp16(__half* dst, const __half* src) {
    unsigned a = (unsigned)__cvta_generic_to_shared(dst);
    asm volatile("cp.async.cg.shared.global [%0], [%1], 16;\n" :: "r"(a), "l"(src));
}
__device__ __forceinline__ void ldm4(unsigned* r, const __half* p) {
    unsigned a = (unsigned)__cvta_generic_to_shared(p);
    asm volatile("ldmatrix.sync.aligned.m8n8.x4.shared.b16 {%0,%1,%2,%3}, [%4];\n"
                 : "=r"(r[0]), "=r"(r[1]), "=r"(r[2]), "=r"(r[3]) : "r"(a));
}
__device__ __forceinline__ void mma16816(float* d, const unsigned* a, const unsigned* b) {
    asm volatile("mma.sync.aligned.m16n8k16.row.col.f32.f16.f16.f32 "
                 "{%0,%1,%2,%3}, {%4,%5,%6,%7}, {%8,%9}, {%0,%1,%2,%3};\n"
                 : "+f"(d[0]), "+f"(d[1]), "+f"(d[2]), "+f"(d[3])
                 : "r"(a[0]), "r"(a[1]), "r"(a[2]), "r"(a[3]), "r"(b[0]), "r"(b[1]));
}
__device__ __forceinline__ int swz(int row, int chunk) {
    return row * 32 + ((chunk ^ ((row >> 1) & 3)) << 3);
}

template<int LA, int TERMS>
__device__ __forceinline__ void load_stage(__half* dst,
        const __half* Ah, const __half* Al,
        const __half* Bh, const __half* Bl,
        int i0, int j0, int kc, int bwA, int bwB, int t) {
    const int B_HI = (TERMS == 3) ? 2 * MSZ : MSZ;
    #pragma unroll
    for (int q = 0; q < 4; q++) {
        int idx = t + q * 128;
        int row = idx >> 2, c = idx & 3;
        int so = swz(row, c);
        int ra = i0 + row;
        int ba = ra / LA, la = ra - ba * LA;
        size_t goA = (size_t)ba * bwA + la * 600 + kc + c * 8;
        size_t goB = (size_t)(j0 + row) * bwB + kc + c * 8;
        cp16(dst + so, Ah + goA);
        if (TERMS == 3) cp16(dst + MSZ + so, Al + goA);
        cp16(dst + B_HI + so, Bh + goB);
        if (TERMS >= 2) cp16(dst + B_HI + MSZ + so, Bl + goB);
    }
}

template<int LA, int TERMS, int STAGES>
__device__ __forceinline__ void gemm_core(
        const __half* Ah, const __half* Al,
        const __half* Bh, const __half* Bl,
        int i0, int j0, int bwA, int bwB, int kIters,
        __half* sm, int t, float acc[4][8][4]) {
    const int STG_T = (TERMS + 1) * MSZ;
    const int B_HI  = (TERMS == 3) ? 2 * MSZ : MSZ;
    int lane = t & 31, wid = t >> 5;
    int wm = wid & 1, wn = wid >> 1;
    int lr = lane & 15, lc = (lane >> 4) << 3;

    #pragma unroll
    for (int s = 0; s < STAGES - 1; s++) {
        if (s < kIters) load_stage<LA, TERMS>(sm + s * STG_T, Ah, Al, Bh, Bl, i0, j0, s * GBK, bwA, bwB, t);
        asm volatile("cp.async.commit_group;\n");
    }
    for (int it = 0; it < kIters; it++) {
        asm volatile("cp.async.wait_group %0;\n" :: "n"(STAGES - 2));
        __syncthreads();
        int nxt = it + STAGES - 1;
        if (nxt < kIters) load_stage<LA, TERMS>(sm + (nxt % STAGES) * STG_T, Ah, Al, Bh, Bl, i0, j0, nxt * GBK, bwA, bwB, t);
        asm volatile("cp.async.commit_group;\n");

        const __half* buf = sm + (it % STAGES) * STG_T;
        const __half* sAh = buf;
        const __half* sAl = buf + MSZ;
        const __half* sBh = buf + B_HI;
        const __half* sBl = buf + B_HI + MSZ;

        #pragma unroll
        for (int ks = 0; ks < GBK; ks += 16) {
            unsigned ah[4][4], al[4][4], bh[8][2], bl[8][2];
            int cl = (ks + lc) >> 3;
            #pragma unroll
            for (int mt = 0; mt < 4; mt++) {
                int rA = wm * 64 + mt * 16 + lr;
                ldm4(ah[mt], sAh + swz(rA, cl));
                if (TERMS == 3) ldm4(al[mt], sAl + swz(rA, cl));
            }
            #pragma unroll
            for (int bt = 0; bt < 4; bt++) {
                int rB = wn * 64 + bt * 16 + lr;
                unsigned r4[4];
                ldm4(r4, sBh + swz(rB, cl));
                bh[2 * bt][0] = r4[0]; bh[2 * bt][1] = r4[2];
                bh[2 * bt + 1][0] = r4[1]; bh[2 * bt + 1][1] = r4[3];
                if (TERMS >= 2) {
                    ldm4(r4, sBl + swz(rB, cl));
                    bl[2 * bt][0] = r4[0]; bl[2 * bt][1] = r4[2];
                    bl[2 * bt + 1][0] = r4[1]; bl[2 * bt + 1][1] = r4[3];
                }
            }
            #pragma unroll
            for (int mt = 0; mt < 4; mt++)
                #pragma unroll
                for (int nt = 0; nt < 8; nt++) {
                    mma16816(acc[mt][nt], ah[mt], bh[nt]);
                    if (TERMS >= 2) mma16816(acc[mt][nt], ah[mt], bl[nt]);
                    if (TERMS == 3) mma16816(acc[mt][nt], al[mt], bh[nt]);
                }
        }
    }
    __syncthreads();
}

// ---------------- symmetric Gram, triu-packed output ----------------
template<int TERMS, int STAGES>
__global__ __launch_bounds__(128, 2)
void k_gram_t(const __half* __restrict__ Xhi, const __half* __restrict__ Xlo,
              int ldk, int kIters, float* __restrict__ out) {
    extern __shared__ __half sm[];
    int p = blockIdx.x;
    int ti = 0, rem = 32;
    while (p >= rem) { p -= rem; rem--; ti++; }
    int tj = ti + p;
    const int i0 = ti * GBM, j0 = tj * GBM;

    int t = threadIdx.x;
    float acc[4][8][4];
    #pragma unroll
    for (int mt = 0; mt < 4; mt++)
        #pragma unroll
        for (int nt = 0; nt < 8; nt++)
            #pragma unroll
            for (int e = 0; e < 4; e++) acc[mt][nt][e] = 0.f;

    gemm_core<1, TERMS, STAGES>(Xhi, Xlo, Xhi, Xlo, i0, j0, ldk, ldk, kIters, sm, t, acc);

    int lane = t & 31, wid = t >> 5;
    int wm = wid & 1, wn = wid >> 1;
    int r = lane >> 2, cp = (lane & 3) * 2;
    #pragma unroll
    for (int mt = 0; mt < 4; mt++) {
        #pragma unroll
        for (int h = 0; h < 2; h++) {
            int i = i0 + wm * 64 + mt * 16 + r + h * 8;
            int base = i * (8191 - i) / 2 - i - 1;
            #pragma unroll
            for (int nt = 0; nt < 8; nt++) {
                int j = j0 + wn * 64 + nt * 8 + cp;
                if (j > i)     out[base + j]     = acc[mt][nt][2 * h + 0];
                if (j + 1 > i) out[base + j + 1] = acc[mt][nt][2 * h + 1];
            }
        }
    }
}

// ---------------- conv GEMM: implicit im2col; MODE 0: bias; MODE 1: bias+tanh -> dst & out2 ----------------
template<int LA, int MODE, int TERMS, int STAGES>
__global__ __launch_bounds__(128, 2)
void k_conv_gemm(const __half* __restrict__ Ah, const __half* __restrict__ Al,
                 const __half* __restrict__ Bh, const __half* __restrict__ Bl,
                 int kIters, int bwA, int bwB, int Cout,
                 const float* __restrict__ bias, float* __restrict__ dst, float* __restrict__ out2) {
    extern __shared__ __half sm[];
    const int n0 = blockIdx.x * GBM, m0 = blockIdx.y * GBM;

    int t = threadIdx.x;
    float acc[4][8][4];
    #pragma unroll
    for (int mt = 0; mt < 4; mt++)
        #pragma unroll
        for (int nt = 0; nt < 8; nt++)
            #pragma unroll
            for (int e = 0; e < 4; e++) acc[mt][nt][e] = 0.f;

    gemm_core<LA, TERMS, STAGES>(Ah, Al, Bh, Bl, m0, n0, bwA, bwB, kIters, sm, t, acc);

    int lane = t & 31, wid = t >> 5;
    int wm = wid & 1, wn = wid >> 1;
    int r = lane >> 2, cp = (lane & 3) * 2;
    #pragma unroll
    for (int mt = 0; mt < 4; mt++) {
        #pragma unroll
        for (int h = 0; h < 2; h++) {
            int m = m0 + wm * 64 + mt * 16 + r + h * 8;
            #pragma unroll
            for (int nt = 0; nt < 8; nt++) {
                int n = n0 + wn * 64 + nt * 8 + cp;
                float a0 = acc[mt][nt][2 * h + 0];
                float a1 = acc[mt][nt][2 * h + 1];
                if (MODE == 0) {
                    if (n < Cout)     dst[(size_t)m * Cout + n]     = a0 + bias[n];
                    if (n + 1 < Cout) dst[(size_t)m * Cout + n + 1] = a1 + bias[n + 1];
                } else {
                    if (n < Cout) {
                        float v = tanhf(a0 + bias[n]);
                        dst[(size_t)m * Cout + n] = v;
                        out2[(size_t)m * Cout + n] = v;
                    }
                    if (n + 1 < Cout) {
                        float v = tanhf(a1 + bias[n + 1]);
                        dst[(size_t)m * Cout + n + 1] = v;
                        out2[(size_t)m * Cout + n + 1] = v;
                    }
                }
            }
        }
    }
}

// ---------------- launch ----------------
extern "C" void kernel_launch(void* const* d_in, const int* in_sizes, int n_in,
                              void* d_out, int out_size) {
    const int*   x   = (const int*)  d_in[0];
    const float* emb = (const float*)d_in[1];
    const float* w1  = (const float*)d_in[2];
    const float* b1  = (const float*)d_in[3];
    const float* w2  = (const float*)d_in[4];
    const float* b2  = (const float*)d_in[5];
    const float* w3  = (const float*)d_in[6];
    const float* b3  = (const float*)d_in[7];
    const float* g1  = (const float*)d_in[8];
    const float* be1 = (const float*)d_in[9];
    const float* g2  = (const float*)d_in[10];
    const float* be2 = (const float*)d_in[11];
    float* out = (float*)d_out;

    const int smem1 = 4 * 2 * MSZ * 2;   // TERMS=1, 4 stages: 65536
    const int smem3 = 3 * 4 * MSZ * 2;   // TERMS=3, 3 stages: 98304
    cudaFuncSetAttribute((const void*)k_gram_t<1,4>,         cudaFuncAttributeMaxDynamicSharedMemorySize, smem1);
    cudaFuncSetAttribute((const void*)k_gram_t<3,3>,         cudaFuncAttributeMaxDynamicSharedMemorySize, smem3);
    cudaFuncSetAttribute((const void*)k_conv_gemm<13,0,1,4>, cudaFuncAttributeMaxDynamicSharedMemorySize, smem1);
    cudaFuncSetAttribute((const void*)k_conv_gemm<5,0,1,4>,  cudaFuncAttributeMaxDynamicSharedMemorySize, smem1);
    cudaFuncSetAttribute((const void*)k_conv_gemm<1,1,3,3>,  cudaFuncAttributeMaxDynamicSharedMemorySize, smem3);

    __half *eh, *w1h, *w2h, *w3h, *w3l;
    __half *h1h, *h2h, *h2l, *fh, *fl;
    float *h1p, *h2p, *finp, *m1p, *i1p, *m2p, *i2p;
    cudaGetSymbolAddress((void**)&eh,  g_Eh);
    cudaGetSymbolAddress((void**)&w1h, g_W1h);
    cudaGetSymbolAddress((void**)&w2h, g_W2h);
    cudaGetSymbolAddress((void**)&w3h, g_W3h);
    cudaGetSymbolAddress((void**)&w3l, g_W3l);
    cudaGetSymbolAddress((void**)&h1h, g_h1h);
    cudaGetSymbolAddress((void**)&h2h, g_h2h);
    cudaGetSymbolAddress((void**)&h2l, g_h2l);
    cudaGetSymbolAddress((void**)&fh,  g_Fnh);
    cudaGetSymbolAddress((void**)&fl,  g_Fnl);
    cudaGetSymbolAddress((void**)&h1p, g_h1);
    cudaGetSymbolAddress((void**)&h2p, g_h2);
    cudaGetSymbolAddress((void**)&finp, g_final);
    cudaGetSymbolAddress((void**)&m1p, g_mean1);
    cudaGetSymbolAddress((void**)&i1p, g_istd1);
    cudaGetSymbolAddress((void**)&m2p, g_mean2);
    cudaGetSymbolAddress((void**)&i2p, g_istd2);

    cudaStream_t s2;
    cudaStreamCreateWithFlags(&s2, cudaStreamNonBlocking);
    cudaEvent_t evPrep, evGather, evJoin;
    cudaEventCreateWithFlags(&evPrep,   cudaEventDisableTiming);
    cudaEventCreateWithFlags(&evGather, cudaEventDisableTiming);
    cudaEventCreateWithFlags(&evJoin,   cudaEventDisableTiming);

    // ---- prologue: gather(+fused renorm) on main; prep_w+padzero concurrently on s2 ----
    cudaEventRecord(evPrep, 0);
    cudaStreamWaitEvent(s2, evPrep, 0);
    k_prep_w<<<1024, 256, 0, s2>>>(w1, w2, w3);
    k_padzero<<<16, 256, 0, s2>>>();
    cudaEventRecord(evPrep, s2);

    k_gather<<<BATCH, 256>>>(x, emb);
    cudaEventRecord(evGather, 0);

    // s2: big input Gram (needs gather + padzero; prep already on s2)
    cudaStreamWaitEvent(s2, evGather, 0);
    k_gram_t<1,4><<<528, 128, smem1, s2>>>(eh, eh, BW_E, BW_E / GBK, out + HOUT);
    cudaEventRecord(evJoin, s2);

    // main: conv chain (needs prep_w + padzero from s2)
    cudaStreamWaitEvent(0, evPrep, 0);
    {
        dim3 g(3, M1 / GBM);
        k_conv_gemm<13,0,1,4><<<g, 128, smem1>>>(eh, eh, w1h, w1h, (K1 + GBK - 1) / GBK, BW_E, K1, C1, b1, h1p, nullptr);
    }
    k_bnstat_p<<<dim3(10, 32), 256>>>(h1p, M1, C1);
    k_bnstat_r<<<2, 256>>>(C1, 1.f / M1, m1p, i1p);
    k_bnapply<<<2048, 256>>>(h1p, h1h, nullptr, m1p, i1p, g1, be1, M1, C1, L1o, 4);

    {
        dim3 g(5, M2 / GBM);
        k_conv_gemm<5,0,1,4><<<g, 128, smem1>>>(h1h, h1h, w2h, w2h, (K1 + GBK - 1) / GBK, BW_H1, K1, C2, b2, h2p, nullptr);
    }
    k_bnstat_p<<<dim3(19, 32), 256>>>(h2p, M2, C2);
    k_bnstat_r<<<3, 256>>>(C2, 1.f / M2, m2p, i2p);
    k_bnapply<<<2048, 256>>>(h2p, h2h, h2l, m2p, i2p, g2, be2, M2, C2, L2o, 8);

    {
        dim3 g(1, BATCH / GBM);
        k_conv_gemm<1,1,3,3><<<g, 128, smem3>>>(h2h, h2l, w3h, w3l, K3 / GBK, BW_H2, K3, C3, b3, finp, out);
    }
    k_norm<<<BATCH * 32 / 256, 256>>>();

    // hidden Gram: 3-term 128-tiles on main stream
    k_gram_t<3,3><<<528, 128, smem3>>>(fh, fl, KPAD_F, KPAD_F / GBK, out + HOUT + NPAIRS);

    // ---- join side stream ----
    cudaStreamWaitEvent(0, evJoin, 0);

    cudaEventDestroy(evPrep);
    cudaEventDestroy(evGather);
    cudaEventDestroy(evJoin);
    cudaStreamDestroy(s2);
}

// round 16
// speedup vs baseline: 1.0066x; 1.0066x over previous
#include <cuda_runtime.h>
#include <cuda_fp16.h>
#include <cstdint>
#include <math.h>

// ---------------- problem constants ----------------
#define BATCH 4096
#define LSEQ  28
#define VOCAB 32000
#define DIM   300
#define BW_E  8704            // per-batch row: 300 front pad + 8400 data + 4 back pad
#define KPAD_F 128
#define K1    1504            // conv1/conv2 GEMM K (1500 padded)
#define K3    3008            // conv3 GEMM K (3000 padded)
#define BW_H1 3904            // 13*300 + 4
#define BW_H2 3008            // 5*600 + 8
#define L1o   13
#define C1    300
#define L2o   5
#define C2    600
#define C3    100
#define M1    (BATCH*L1o)     // 53248 = 416*128
#define M2    (BATCH*L2o)     // 20480 = 160*128
#define NPAIRS 8386560
#define HOUT  (BATCH*C3)

// ---------------- scratch (lo-buffers kept ONLY where actually read) ----------------
__device__ __half g_Eh[(size_t)BATCH*BW_E + 64];
__device__ __half g_W1h[384*K1];
__device__ __half g_W2h[640*K1];
__device__ __half g_W3h[128*K3], g_W3l[128*K3];
__device__ float g_h1[(size_t)M1*C1];
__device__ float g_h2[(size_t)M2*C2];
__device__ __half g_h1h[(size_t)BATCH*BW_H1 + 64];
__device__ __half g_h2h[(size_t)BATCH*BW_H2 + 64], g_h2l[(size_t)BATCH*BW_H2 + 64];
__device__ float g_final[BATCH*C3];
__device__ __half g_Fnh[BATCH*KPAD_F], g_Fnl[BATCH*KPAD_F];
__device__ float g_mean1[C1], g_istd1[C1];
__device__ float g_mean2[C2], g_istd2[C2];
__device__ float g_part[32*640*2];

// ---------------- gather + fused renorm into position-major E_T (hi only) ----------------
__global__ __launch_bounds__(256)
void k_gather(const int* __restrict__ x, const float* __restrict__ emb) {
    __shared__ float sx[LSEQ * DIM];     // 33.6 KB
    __shared__ int   tok[LSEQ];
    __shared__ float nrm[LSEQ];
    int b = blockIdx.x, t = threadIdx.x;
    int lane = t & 31, wid = t >> 5;
    bool is64 = (x[1] == 0 && x[3] == 0 && x[5] == 0 && x[7] == 0);
    if (t < LSEQ) {
        tok[t] = is64 ? x[(b * LSEQ + t) * 2] : x[b * LSEQ + t];
    }
    __syncthreads();
    #pragma unroll
    for (int l = 0; l < LSEQ; l++) {
        const float* row = emb + (size_t)tok[l] * DIM;
        for (int ci = t; ci < DIM; ci += 256) sx[l * DIM + ci] = row[ci];
    }
    __syncthreads();
    for (int l = wid; l < LSEQ; l += 8) {
        float s = 0.f;
        for (int d = lane; d < DIM; d += 32) { float v = sx[l * DIM + d]; s += v * v; }
        #pragma unroll
        for (int o = 16; o; o >>= 1) s += __shfl_xor_sync(0xffffffffu, s, o);
        if (lane == 0) nrm[l] = fminf(1.f, 1.f / (sqrtf(s) + 1e-7f));
    }
    __syncthreads();
    __half* dH = g_Eh + (size_t)b * BW_E;
    const __half z = __float2half_rn(0.f);
    for (int i = t; i < 304; i += 256) {
        int o = (i < 300) ? i : (8400 + i);
        dH[o] = z;
    }
    #pragma unroll
    for (int l = 0; l < LSEQ; l++) {
        float sc = nrm[l];
        for (int ci = t; ci < DIM; ci += 256)
            dH[300 + l * DIM + ci] = __float2half_rn(sx[l * DIM + ci] * sc);
    }
}

// ---------------- weight prep (w1/w2 hi only; w3 split) ----------------
__global__ void k_prep_w(const float* __restrict__ w1, const float* __restrict__ w2,
                         const float* __restrict__ w3) {
    const int n1 = 384 * K1, n2 = 640 * K1, n3 = 128 * K3;
    int total = n1 + n2 + n3;
    for (int idx = blockIdx.x * blockDim.x + threadIdx.x; idx < total; idx += gridDim.x * blockDim.x) {
        int i = idx;
        if (i < n1) {
            int n = i / K1, k = i - n * K1;
            int kk = k / 300, ci = k - kk * 300;
            float v = (n < C1 && kk < 5) ? w1[n * 1500 + ci * 5 + kk] : 0.f;
            g_W1h[i] = __float2half_rn(v);
            continue;
        }
        i -= n1;
        if (i < n2) {
            int n = i / K1, k = i - n * K1;
            int kk = k / 300, ci = k - kk * 300;
            float v = (n < C2 && kk < 5) ? w2[n * 1500 + ci * 5 + kk] : 0.f;
            g_W2h[i] = __float2half_rn(v);
            continue;
        }
        i -= n2;
        {
            int n = i / K3, k = i - n * K3;
            int kk = k / 600, ci = k - kk * 600;
            float v = (n < C3 && kk < 5) ? w3[n * 3000 + ci * 5 + kk] : 0.f;
            __half h = __float2half_rn(v);
            g_W3h[i] = h;
            g_W3l[i] = __float2half_rn(v - __half2float(h));
        }
    }
}

// ---------------- zero tail pads ----------------
__global__ void k_padzero() {
    int b = blockIdx.x * blockDim.x + threadIdx.x;
    const __half z = __float2half_rn(0.f);
    if (b < BATCH) {
        #pragma unroll
        for (int i = 0; i < 4; i++) {
            g_h1h[(size_t)b * BW_H1 + 3900 + i] = z;
        }
        #pragma unroll
        for (int i = 0; i < 8; i++) {
            g_h2h[(size_t)b * BW_H2 + 3000 + i] = z;
            g_h2l[(size_t)b * BW_H2 + 3000 + i] = z;
        }
    }
    if (b < 64) {
        g_Eh[(size_t)BATCH * BW_E + b]   = z;
        g_h1h[(size_t)BATCH * BW_H1 + b] = z;
        g_h2h[(size_t)BATCH * BW_H2 + b] = z;
        g_h2l[(size_t)BATCH * BW_H2 + b] = z;
    }
}

// ---------------- BN stats ----------------
__global__ void k_bnstat_p(const float* __restrict__ h, int M, int C) {
    int lane = threadIdx.x & 31;
    int w = threadIdx.x >> 5;
    int c = blockIdx.x * 32 + lane;
    int chunk = blockIdx.y;
    int rpc = M >> 5;
    float s = 0.f, s2 = 0.f;
    if (c < C) {
        int r1 = (chunk + 1) * rpc;
        for (int r = chunk * rpc + w; r < r1; r += 8) {
            float v = h[(size_t)r * C + c];
            s += v; s2 += v * v;
        }
    }
    __shared__ float sh[8][32][2];
    sh[w][lane][0] = s; sh[w][lane][1] = s2;
    __syncthreads();
    if (threadIdx.x < 32) {
        float S = 0.f, S2 = 0.f;
        #pragma unroll
        for (int i = 0; i < 8; i++) { S += sh[i][threadIdx.x][0]; S2 += sh[i][threadIdx.x][1]; }
        int cc = blockIdx.x * 32 + threadIdx.x;
        if (cc < C) {
            g_part[(chunk * 640 + cc) * 2 + 0] = S;
            g_part[(chunk * 640 + cc) * 2 + 1] = S2;
        }
    }
}

__global__ void k_bnstat_r(int C, float invN, float* __restrict__ mean, float* __restrict__ istd) {
    int c = blockIdx.x * blockDim.x + threadIdx.x;
    if (c >= C) return;
    float S = 0.f, S2 = 0.f;
    for (int ch = 0; ch < 32; ch++) {
        S  += g_part[(ch * 640 + c) * 2 + 0];
        S2 += g_part[(ch * 640 + c) * 2 + 1];
    }
    float m = S * invN;
    mean[c] = m;
    istd[c] = rsqrtf(S2 * invN - m * m + 1e-5f);
}

// ---------------- BN apply + ReLU + fp16 (optionally split) into padded T layout ----------------
__global__ void k_bnapply(const float* __restrict__ h, __half* __restrict__ oh,
                          __half* __restrict__ ol,
                          const float* __restrict__ mean, const float* __restrict__ istd,
                          const float* __restrict__ gamma, const float* __restrict__ beta,
                          int M, int C, int lout, int pad) {
    size_t total = (size_t)M * C;
    size_t stride = (size_t)gridDim.x * blockDim.x;
    for (size_t idx = (size_t)blockIdx.x * blockDim.x + threadIdx.x; idx < total; idx += stride) {
        int m = (int)(idx / C), c = (int)(idx - (size_t)m * C);
        float v = (h[idx] - mean[c]) * istd[c] * gamma[c] + beta[c];
        v = fmaxf(v, 0.f);
        size_t off = idx + (size_t)pad * (m / lout);
        __half hi = __float2half_rn(v);
        oh[off] = hi;
        if (ol) ol[off] = __float2half_rn(v - __half2float(hi));
    }
}

// ---------------- row-normalize final -> fp16 hi/lo ----------------
__global__ void k_norm() {
    int gw = (blockIdx.x * blockDim.x + threadIdx.x) >> 5;
    int lane = threadIdx.x & 31;
    if (gw >= BATCH) return;
    const float* f = g_final + gw * C3;
    float s = 0.f;
    for (int c = lane; c < C3; c += 32) { float v = f[c]; s += v * v; }
    #pragma unroll
    for (int o = 16; o; o >>= 1) s += __shfl_xor_sync(0xffffffffu, s, o);
    float n = sqrtf(s);
    __half* oh = g_Fnh + gw * KPAD_F;
    __half* ol = g_Fnl + gw * KPAD_F;
    for (int c = lane; c < C3; c += 32) {
        float v = f[c] / n;
        __half h = __float2half_rn(v);
        oh[c] = h;
        ol[c] = __float2half_rn(v - __half2float(h));
    }
    for (int c = C3 + lane; c < KPAD_F; c += 32) {
        oh[c] = __float2half_rn(0.f);
        ol[c] = __float2half_rn(0.f);
    }
}

// ================= HMMA GEMM machinery (split-fp16, swizzled smem) =================
// CTA 128x128, 128 threads = 4 warps of 64x64. 3-stage cp.async pipeline, Kc=32.
// TERMS=3: C = Ah*Bh + Ah*Bl + Al*Bh ; TERMS=2: + Ah*Bl ; TERMS=1: Ah*Bh only
#define GBM 128
#define GBK 32
#define GSTAGES 3
#define MSZ (128*32)

__device__ __forceinline__ void cp16(__half* dst, const __half* src) {
    unsigned a = (unsigned)__cvta_generic_to_shared(dst);
    asm volatile("cp.async.cg.shared.global [%0], [%1], 16;\n" :: "r"(a), "l"(src));
}
__device__ __forceinline__ void ldm4(unsigned* r, const __half* p) {
    unsigned a = (unsigned)__cvta_generic_to_shared(p);
    asm volatile("ldmatrix.sync.aligned.m8n8.x4.shared.b16 {%0,%1,%2,%3}, [%4];\n"
                 : "=r"(r[0]), "=r"(r[1]), "=r"(r[2]), "=r"(r[3]) : "r"(a));
}
__device__ __forceinline__ void mma16816(float* d, const unsigned* a, const unsigned* b) {
    asm volatile("mma.sync.aligned.m16n8k16.row.col.f32.f16.f16.f32 "
                 "{%0,%1,%2,%3}, {%4,%5,%6,%7}, {%8,%9}, {%0,%1,%2,%3};\n"
                 : "+f"(d[0]), "+f"(d[1]), "+f"(d[2]), "+f"(d[3])
                 : "r"(a[0]), "r"(a[1]), "r"(a[2]), "r"(a[3]), "r"(b[0]), "r"(b[1]));
}
__device__ __forceinline__ int swz(int row, int chunk) {
    return row * 32 + ((chunk ^ ((row >> 1) & 3)) << 3);
}

template<int LA, int TERMS>
__device__ __forceinline__ void load_stage(__half* dst,
        const __half* Ah, const __half* Al,
        const __half* Bh, const __half* Bl,
        int i0, int j0, int kc, int bwA, int bwB, int t) {
    const int B_HI = (TERMS == 3) ? 2 * MSZ : MSZ;
    #pragma unroll
    for (int q = 0; q < 4; q++) {
        int idx = t + q * 128;
        int row = idx >> 2, c = idx & 3;
        int so = swz(row, c);
        int ra = i0 + row;
        int ba = ra / LA, la = ra - ba * LA;
        size_t goA = (size_t)ba * bwA + la * 600 + kc + c * 8;
        size_t goB = (size_t)(j0 + row) * bwB + kc + c * 8;
        cp16(dst + so, Ah + goA);
        if (TERMS == 3) cp16(dst + MSZ + so, Al + goA);
        cp16(dst + B_HI + so, Bh + goB);
        if (TERMS >= 2) cp16(dst + B_HI + MSZ + so, Bl + goB);
    }
}

template<int LA, int TERMS>
__device__ __forceinline__ void gemm_core(
        const __half* Ah, const __half* Al,
        const __half* Bh, const __half* Bl,
        int i0, int j0, int bwA, int bwB, int kIters,
        __half* sm, int t, float acc[4][8][4]) {
    const int STG_T = (TERMS + 1) * MSZ;
    const int B_HI  = (TERMS == 3) ? 2 * MSZ : MSZ;
    int lane = t & 31, wid = t >> 5;
    int wm = wid & 1, wn = wid >> 1;
    int lr = lane & 15, lc = (lane >> 4) << 3;

    #pragma unroll
    for (int s = 0; s < GSTAGES - 1; s++) {
        if (s < kIters) load_stage<LA, TERMS>(sm + s * STG_T, Ah, Al, Bh, Bl, i0, j0, s * GBK, bwA, bwB, t);
        asm volatile("cp.async.commit_group;\n");
    }
    for (int it = 0; it < kIters; it++) {
        asm volatile("cp.async.wait_group %0;\n" :: "n"(GSTAGES - 2));
        __syncthreads();
        int nxt = it + GSTAGES - 1;
        if (nxt < kIters) load_stage<LA, TERMS>(sm + (nxt % GSTAGES) * STG_T, Ah, Al, Bh, Bl, i0, j0, nxt * GBK, bwA, bwB, t);
        asm volatile("cp.async.commit_group;\n");

        const __half* buf = sm + (it % GSTAGES) * STG_T;
        const __half* sAh = buf;
        const __half* sAl = buf + MSZ;
        const __half* sBh = buf + B_HI;
        const __half* sBl = buf + B_HI + MSZ;

        #pragma unroll
        for (int ks = 0; ks < GBK; ks += 16) {
            unsigned ah[4][4], al[4][4], bh[8][2], bl[8][2];
            int cl = (ks + lc) >> 3;
            #pragma unroll
            for (int mt = 0; mt < 4; mt++) {
                int rA = wm * 64 + mt * 16 + lr;
                ldm4(ah[mt], sAh + swz(rA, cl));
                if (TERMS == 3) ldm4(al[mt], sAl + swz(rA, cl));
            }
            #pragma unroll
            for (int bt = 0; bt < 4; bt++) {
                int rB = wn * 64 + bt * 16 + lr;
                unsigned r4[4];
                ldm4(r4, sBh + swz(rB, cl));
                bh[2 * bt][0] = r4[0]; bh[2 * bt][1] = r4[2];
                bh[2 * bt + 1][0] = r4[1]; bh[2 * bt + 1][1] = r4[3];
                if (TERMS >= 2) {
                    ldm4(r4, sBl + swz(rB, cl));
                    bl[2 * bt][0] = r4[0]; bl[2 * bt][1] = r4[2];
                    bl[2 * bt + 1][0] = r4[1]; bl[2 * bt + 1][1] = r4[3];
                }
            }
            #pragma unroll
            for (int mt = 0; mt < 4; mt++)
                #pragma unroll
                for (int nt = 0; nt < 8; nt++) {
                    mma16816(acc[mt][nt], ah[mt], bh[nt]);
                    if (TERMS >= 2) mma16816(acc[mt][nt], ah[mt], bl[nt]);
                    if (TERMS == 3) mma16816(acc[mt][nt], al[mt], bh[nt]);
                }
        }
    }
    __syncthreads();
}

// ---------------- symmetric Gram, triu-packed output ----------------
template<int TERMS>
__global__ __launch_bounds__(128, 2)
void k_gram_t(const __half* __restrict__ Xhi, const __half* __restrict__ Xlo,
              int ldk, int kIters, float* __restrict__ out) {
    extern __shared__ __half sm[];
    int p = blockIdx.x;
    int ti = 0, rem = 32;
    while (p >= rem) { p -= rem; rem--; ti++; }
    int tj = ti + p;
    const int i0 = ti * GBM, j0 = tj * GBM;

    int t = threadIdx.x;
    float acc[4][8][4];
    #pragma unroll
    for (int mt = 0; mt < 4; mt++)
        #pragma unroll
        for (int nt = 0; nt < 8; nt++)
            #pragma unroll
            for (int e = 0; e < 4; e++) acc[mt][nt][e] = 0.f;

    gemm_core<1, TERMS>(Xhi, Xlo, Xhi, Xlo, i0, j0, ldk, ldk, kIters, sm, t, acc);

    int lane = t & 31, wid = t >> 5;
    int wm = wid & 1, wn = wid >> 1;
    int r = lane >> 2, cp = (lane & 3) * 2;
    #pragma unroll
    for (int mt = 0; mt < 4; mt++) {
        #pragma unroll
        for (int h = 0; h < 2; h++) {
            int i = i0 + wm * 64 + mt * 16 + r + h * 8;
            int base = i * (8191 - i) / 2 - i - 1;
            #pragma unroll
            for (int nt = 0; nt < 8; nt++) {
                int j = j0 + wn * 64 + nt * 8 + cp;
                if (j > i)     out[base + j]     = acc[mt][nt][2 * h + 0];
                if (j + 1 > i) out[base + j + 1] = acc[mt][nt][2 * h + 1];
            }
        }
    }
}

// ---------------- conv GEMM: implicit im2col; MODE 0: bias; MODE 1: bias+tanh -> dst & out2 ----------------
template<int LA, int MODE, int TERMS>
__global__ __launch_bounds__(128, 2)
void k_conv_gemm(const __half* __restrict__ Ah, const __half* __restrict__ Al,
                 const __half* __restrict__ Bh, const __half* __restrict__ Bl,
                 int kIters, int bwA, int bwB, int Cout,
                 const float* __restrict__ bias, float* __restrict__ dst, float* __restrict__ out2) {
    extern __shared__ __half sm[];
    const int n0 = blockIdx.x * GBM, m0 = blockIdx.y * GBM;

    int t = threadIdx.x;
    float acc[4][8][4];
    #pragma unroll
    for (int mt = 0; mt < 4; mt++)
        #pragma unroll
        for (int nt = 0; nt < 8; nt++)
            #pragma unroll
            for (int e = 0; e < 4; e++) acc[mt][nt][e] = 0.f;

    gemm_core<LA, TERMS>(Ah, Al, Bh, Bl, m0, n0, bwA, bwB, kIters, sm, t, acc);

    int lane = t & 31, wid = t >> 5;
    int wm = wid & 1, wn = wid >> 1;
    int r = lane >> 2, cp = (lane & 3) * 2;
    #pragma unroll
    for (int mt = 0; mt < 4; mt++) {
        #pragma unroll
        for (int h = 0; h < 2; h++) {
            int m = m0 + wm * 64 + mt * 16 + r + h * 8;
            #pragma unroll
            for (int nt = 0; nt < 8; nt++) {
                int n = n0 + wn * 64 + nt * 8 + cp;
                float a0 = acc[mt][nt][2 * h + 0];
                float a1 = acc[mt][nt][2 * h + 1];
                if (MODE == 0) {
                    if (n < Cout)     dst[(size_t)m * Cout + n]     = a0 + bias[n];
                    if (n + 1 < Cout) dst[(size_t)m * Cout + n + 1] = a1 + bias[n + 1];
                } else {
                    if (n < Cout) {
                        float v = tanhf(a0 + bias[n]);
                        dst[(size_t)m * Cout + n] = v;
                        out2[(size_t)m * Cout + n] = v;
                    }
                    if (n + 1 < Cout) {
                        float v = tanhf(a1 + bias[n + 1]);
                        dst[(size_t)m * Cout + n + 1] = v;
                        out2[(size_t)m * Cout + n + 1] = v;
                    }
                }
            }
        }
    }
}

// ---------------- launch ----------------
extern "C" void kernel_launch(void* const* d_in, const int* in_sizes, int n_in,
                              void* d_out, int out_size) {
    const int*   x   = (const int*)  d_in[0];
    const float* emb = (const float*)d_in[1];
    const float* w1  = (const float*)d_in[2];
    const float* b1  = (const float*)d_in[3];
    const float* w2  = (const float*)d_in[4];
    const float* b2  = (const float*)d_in[5];
    const float* w3  = (const float*)d_in[6];
    const float* b3  = (const float*)d_in[7];
    const float* g1  = (const float*)d_in[8];
    const float* be1 = (const float*)d_in[9];
    const float* g2  = (const float*)d_in[10];
    const float* be2 = (const float*)d_in[11];
    float* out = (float*)d_out;

    const int smem1 = GSTAGES * 2 * MSZ * 2;   // TERMS=1: 49152
    const int smem3 = GSTAGES * 4 * MSZ * 2;   // TERMS=3: 98304
    cudaFuncSetAttribute(k_gram_t<1>,           cudaFuncAttributeMaxDynamicSharedMemorySize, smem1);
    cudaFuncSetAttribute(k_gram_t<3>,           cudaFuncAttributeMaxDynamicSharedMemorySize, smem3);
    cudaFuncSetAttribute(k_conv_gemm<13,0,1>,   cudaFuncAttributeMaxDynamicSharedMemorySize, smem1);
    cudaFuncSetAttribute(k_conv_gemm<5,0,1>,    cudaFuncAttributeMaxDynamicSharedMemorySize, smem1);
    cudaFuncSetAttribute(k_conv_gemm<1,1,3>,    cudaFuncAttributeMaxDynamicSharedMemorySize, smem3);

    __half *eh, *w1h, *w2h, *w3h, *w3l;
    __half *h1h, *h2h, *h2l, *fh, *fl;
    float *h1p, *h2p, *finp, *m1p, *i1p, *m2p, *i2p;
    cudaGetSymbolAddress((void**)&eh,  g_Eh);
    cudaGetSymbolAddress((void**)&w1h, g_W1h);
    cudaGetSymbolAddress((void**)&w2h, g_W2h);
    cudaGetSymbolAddress((void**)&w3h, g_W3h);
    cudaGetSymbolAddress((void**)&w3l, g_W3l);
    cudaGetSymbolAddress((void**)&h1h, g_h1h);
    cudaGetSymbolAddress((void**)&h2h, g_h2h);
    cudaGetSymbolAddress((void**)&h2l, g_h2l);
    cudaGetSymbolAddress((void**)&fh,  g_Fnh);
    cudaGetSymbolAddress((void**)&fl,  g_Fnl);
    cudaGetSymbolAddress((void**)&h1p, g_h1);
    cudaGetSymbolAddress((void**)&h2p, g_h2);
    cudaGetSymbolAddress((void**)&finp, g_final);
    cudaGetSymbolAddress((void**)&m1p, g_mean1);
    cudaGetSymbolAddress((void**)&i1p, g_istd1);
    cudaGetSymbolAddress((void**)&m2p, g_mean2);
    cudaGetSymbolAddress((void**)&i2p, g_istd2);

    cudaStream_t s2;
    cudaStreamCreateWithFlags(&s2, cudaStreamNonBlocking);
    cudaEvent_t evPrep, evGather, evJoin;
    cudaEventCreateWithFlags(&evPrep,   cudaEventDisableTiming);
    cudaEventCreateWithFlags(&evGather, cudaEventDisableTiming);
    cudaEventCreateWithFlags(&evJoin,   cudaEventDisableTiming);

    // ---- prologue: gather(+fused renorm) on main; prep_w+padzero concurrently on s2 ----
    cudaEventRecord(evPrep, 0);
    cudaStreamWaitEvent(s2, evPrep, 0);
    k_prep_w<<<1024, 256, 0, s2>>>(w1, w2, w3);
    k_padzero<<<16, 256, 0, s2>>>();
    cudaEventRecord(evPrep, s2);

    k_gather<<<BATCH, 256>>>(x, emb);
    cudaEventRecord(evGather, 0);

    // s2: big input Gram (needs gather + padzero; prep already on s2)
    cudaStreamWaitEvent(s2, evGather, 0);
    k_gram_t<1><<<528, 128, smem1, s2>>>(eh, eh, BW_E, BW_E / GBK, out + HOUT);
    cudaEventRecord(evJoin, s2);

    // main: conv chain (needs prep_w + padzero from s2)
    cudaStreamWaitEvent(0, evPrep, 0);
    {
        dim3 g(3, M1 / GBM);
        k_conv_gemm<13,0,1><<<g, 128, smem1>>>(eh, eh, w1h, w1h, (K1 + GBK - 1) / GBK, BW_E, K1, C1, b1, h1p, nullptr);
    }
    k_bnstat_p<<<dim3(10, 32), 256>>>(h1p, M1, C1);
    k_bnstat_r<<<2, 256>>>(C1, 1.f / M1, m1p, i1p);
    k_bnapply<<<2048, 256>>>(h1p, h1h, nullptr, m1p, i1p, g1, be1, M1, C1, L1o, 4);

    {
        dim3 g(5, M2 / GBM);
        k_conv_gemm<5,0,1><<<g, 128, smem1>>>(h1h, h1h, w2h, w2h, (K1 + GBK - 1) / GBK, BW_H1, K1, C2, b2, h2p, nullptr);
    }
    k_bnstat_p<<<dim3(19, 32), 256>>>(h2p, M2, C2);
    k_bnstat_r<<<3, 256>>>(C2, 1.f / M2, m2p, i2p);
    k_bnapply<<<2048, 256>>>(h2p, h2h, h2l, m2p, i2p, g2, be2, M2, C2, L2o, 8);

    {
        dim3 g(1, BATCH / GBM);
        k_conv_gemm<1,1,3><<<g, 128, smem3>>>(h2h, h2l, w3h, w3l, K3 / GBK, BW_H2, K3, C3, b3, finp, out);
    }
    k_norm<<<BATCH * 32 / 256, 256>>>();

    // hidden Gram: 3-term 128-tiles on main stream
    k_gram_t<3><<<528, 128, smem3>>>(fh, fl, KPAD_F, KPAD_F / GBK, out + HOUT + NPAIRS);

    // ---- join side stream ----
    cudaStreamWaitEvent(0, evJoin, 0);

    cudaEventDestroy(evPrep);
    cudaEventDestroy(evGather);
    cudaEventDestroy(evJoin);
    cudaStreamDestroy(s2);
}

// round 17
// speedup vs baseline: 1.1386x; 1.1311x over previous
#include <cuda_runtime.h>
#include <cuda_fp16.h>
#include <cstdint>
#include <math.h>

// ---------------- problem constants ----------------
#define BATCH 4096
#define LSEQ  28
#define VOCAB 32000
#define DIM   300
#define BW_E  8704            // per-batch row: 300 front pad + 8400 data + 4 back pad (8704 = 136*64)
#define KPAD_F 128
#define K1C   1536            // conv1/conv2 GEMM K (1500 padded to 64-multiple)
#define K3    3008            // conv3 GEMM K (3000 padded, 94*32)
#define BW_H1 3904            // 13*300 + 4
#define BW_H2 3008            // 5*600 + 8
#define L1o   13
#define C1    300
#define L2o   5
#define C2    600
#define C3    100
#define M1    (BATCH*L1o)     // 53248
#define M2    (BATCH*L2o)     // 20480
#define NPAIRS 8386560
#define HOUT  (BATCH*C3)

// ---------------- scratch (lo-buffers only where read) ----------------
__device__ __half g_Eh[(size_t)BATCH*BW_E + 64];
__device__ __half g_W1h[384*K1C];
__device__ __half g_W2h[640*K1C];
__device__ __half g_W3h[128*K3], g_W3l[128*K3];
__device__ float g_h1[(size_t)M1*C1];
__device__ float g_h2[(size_t)M2*C2];
__device__ __half g_h1h[(size_t)BATCH*BW_H1 + 64];
__device__ __half g_h2h[(size_t)BATCH*BW_H2 + 64], g_h2l[(size_t)BATCH*BW_H2 + 64];
__device__ float g_final[BATCH*C3];
__device__ __half g_Fnh[BATCH*KPAD_F], g_Fnl[BATCH*KPAD_F];
__device__ float g_scales[VOCAB];
__device__ float g_mean1[C1], g_istd1[C1];
__device__ float g_mean2[C2], g_istd2[C2];
__device__ float g_part[32*640*2];

// ---------------- embedding renorm scales (R13 form) ----------------
__global__ void k_scales(const float* __restrict__ emb) {
    int warp = (blockIdx.x * blockDim.x + threadIdx.x) >> 5;
    int lane = threadIdx.x & 31;
    if (warp >= VOCAB) return;
    const float* row = emb + (size_t)warp * DIM;
    float s = 0.f;
    for (int d = lane; d < DIM; d += 32) { float v = row[d]; s += v * v; }
    #pragma unroll
    for (int o = 16; o; o >>= 1) s += __shfl_xor_sync(0xffffffffu, s, o);
    if (lane == 0) g_scales[warp] = fminf(1.f, 1.f / (sqrtf(s) + 1e-7f));
}

// ---------------- gather into position-major E_T (hi only; R13 form) ----------------
__global__ void k_gather(const int* __restrict__ x, const float* __restrict__ emb) {
    __shared__ int   tok[LSEQ];
    __shared__ float sc[LSEQ];
    int b = blockIdx.x, t = threadIdx.x;
    bool is64 = (x[1] == 0 && x[3] == 0 && x[5] == 0 && x[7] == 0);
    if (t < LSEQ) {
        int v = is64 ? x[(b * LSEQ + t) * 2] : x[b * LSEQ + t];
        tok[t] = v;
        sc[t]  = g_scales[v];
    }
    __syncthreads();
    __half* dH = g_Eh + (size_t)b * BW_E;
    const __half z = __float2half_rn(0.f);
    for (int i = t; i < 304; i += blockDim.x) {
        int o = (i < 300) ? i : (8400 + i);
        dH[o] = z;
    }
    for (int i = t; i < DIM * LSEQ; i += blockDim.x) {
        int l = i / DIM, ci = i - l * DIM;
        float v = emb[(size_t)tok[l] * DIM + ci] * sc[l];
        dH[300 + i] = __float2half_rn(v);
    }
}

// ---------------- weight prep (w1/w2 hi only, K padded to 1536; w3 split) ----------------
__global__ void k_prep_w(const float* __restrict__ w1, const float* __restrict__ w2,
                         const float* __restrict__ w3) {
    const int n1 = 384 * K1C, n2 = 640 * K1C, n3 = 128 * K3;
    int total = n1 + n2 + n3;
    for (int idx = blockIdx.x * blockDim.x + threadIdx.x; idx < total; idx += gridDim.x * blockDim.x) {
        int i = idx;
        if (i < n1) {
            int n = i / K1C, k = i - n * K1C;
            int kk = k / 300, ci = k - kk * 300;
            float v = (n < C1 && kk < 5) ? w1[n * 1500 + ci * 5 + kk] : 0.f;
            g_W1h[i] = __float2half_rn(v);
            continue;
        }
        i -= n1;
        if (i < n2) {
            int n = i / K1C, k = i - n * K1C;
            int kk = k / 300, ci = k - kk * 300;
            float v = (n < C2 && kk < 5) ? w2[n * 1500 + ci * 5 + kk] : 0.f;
            g_W2h[i] = __float2half_rn(v);
            continue;
        }
        i -= n2;
        {
            int n = i / K3, k = i - n * K3;
            int kk = k / 600, ci = k - kk * 600;
            float v = (n < C3 && kk < 5) ? w3[n * 3000 + ci * 5 + kk] : 0.f;
            __half h = __float2half_rn(v);
            g_W3h[i] = h;
            g_W3l[i] = __float2half_rn(v - __half2float(h));
        }
    }
}

// ---------------- zero tail pads ----------------
__global__ void k_padzero() {
    int b = blockIdx.x * blockDim.x + threadIdx.x;
    const __half z = __float2half_rn(0.f);
    if (b < BATCH) {
        #pragma unroll
        for (int i = 0; i < 4; i++) g_h1h[(size_t)b * BW_H1 + 3900 + i] = z;
        #pragma unroll
        for (int i = 0; i < 8; i++) {
            g_h2h[(size_t)b * BW_H2 + 3000 + i] = z;
            g_h2l[(size_t)b * BW_H2 + 3000 + i] = z;
        }
    }
    if (b < 64) {
        g_Eh[(size_t)BATCH * BW_E + b]   = z;
        g_h1h[(size_t)BATCH * BW_H1 + b] = z;
        g_h2h[(size_t)BATCH * BW_H2 + b] = z;
        g_h2l[(size_t)BATCH * BW_H2 + b] = z;
    }
}

// ---------------- BN stats ----------------
__global__ void k_bnstat_p(const float* __restrict__ h, int M, int C) {
    int lane = threadIdx.x & 31;
    int w = threadIdx.x >> 5;
    int c = blockIdx.x * 32 + lane;
    int chunk = blockIdx.y;
    int rpc = M >> 5;
    float s = 0.f, s2 = 0.f;
    if (c < C) {
        int r1 = (chunk + 1) * rpc;
        for (int r = chunk * rpc + w; r < r1; r += 8) {
            float v = h[(size_t)r * C + c];
            s += v; s2 += v * v;
        }
    }
    __shared__ float sh[8][32][2];
    sh[w][lane][0] = s; sh[w][lane][1] = s2;
    __syncthreads();
    if (threadIdx.x < 32) {
        float S = 0.f, S2 = 0.f;
        #pragma unroll
        for (int i = 0; i < 8; i++) { S += sh[i][threadIdx.x][0]; S2 += sh[i][threadIdx.x][1]; }
        int cc = blockIdx.x * 32 + threadIdx.x;
        if (cc < C) {
            g_part[(chunk * 640 + cc) * 2 + 0] = S;
            g_part[(chunk * 640 + cc) * 2 + 1] = S2;
        }
    }
}

__global__ void k_bnstat_r(int C, float invN, float* __restrict__ mean, float* __restrict__ istd) {
    int c = blockIdx.x * blockDim.x + threadIdx.x;
    if (c >= C) return;
    float S = 0.f, S2 = 0.f;
    for (int ch = 0; ch < 32; ch++) {
        S  += g_part[(ch * 640 + c) * 2 + 0];
        S2 += g_part[(ch * 640 + c) * 2 + 1];
    }
    float m = S * invN;
    mean[c] = m;
    istd[c] = rsqrtf(S2 * invN - m * m + 1e-5f);
}

// ---------------- BN apply + ReLU + fp16 (optionally split) ----------------
__global__ void k_bnapply(const float* __restrict__ h, __half* __restrict__ oh,
                          __half* __restrict__ ol,
                          const float* __restrict__ mean, const float* __restrict__ istd,
                          const float* __restrict__ gamma, const float* __restrict__ beta,
                          int M, int C, int lout, int pad) {
    size_t total = (size_t)M * C;
    size_t stride = (size_t)gridDim.x * blockDim.x;
    for (size_t idx = (size_t)blockIdx.x * blockDim.x + threadIdx.x; idx < total; idx += stride) {
        int m = (int)(idx / C), c = (int)(idx - (size_t)m * C);
        float v = (h[idx] - mean[c]) * istd[c] * gamma[c] + beta[c];
        v = fmaxf(v, 0.f);
        size_t off = idx + (size_t)pad * (m / lout);
        __half hi = __float2half_rn(v);
        oh[off] = hi;
        if (ol) ol[off] = __float2half_rn(v - __half2float(hi));
    }
}

// ---------------- row-normalize final -> fp16 hi/lo ----------------
__global__ void k_norm() {
    int gw = (blockIdx.x * blockDim.x + threadIdx.x) >> 5;
    int lane = threadIdx.x & 31;
    if (gw >= BATCH) return;
    const float* f = g_final + gw * C3;
    float s = 0.f;
    for (int c = lane; c < C3; c += 32) { float v = f[c]; s += v * v; }
    #pragma unroll
    for (int o = 16; o; o >>= 1) s += __shfl_xor_sync(0xffffffffu, s, o);
    float n = sqrtf(s);
    __half* oh = g_Fnh + gw * KPAD_F;
    __half* ol = g_Fnl + gw * KPAD_F;
    for (int c = lane; c < C3; c += 32) {
        float v = f[c] / n;
        __half h = __float2half_rn(v);
        oh[c] = h;
        ol[c] = __float2half_rn(v - __half2float(h));
    }
    for (int c = C3 + lane; c < KPAD_F; c += 32) {
        oh[c] = __float2half_rn(0.f);
        ol[c] = __float2half_rn(0.f);
    }
}

// ================= HMMA GEMM machinery (split-fp16, swizzled smem) =================
// CTA 128x128, 128 threads = 4 warps of 64x64. 3-stage cp.async pipeline.
// KB = K-block (32 or 64). TERMS as before.
#define GBM 128
#define GSTAGES 3

__device__ __forceinline__ void cp16(__half* dst, const __half* src) {
    unsigned a = (unsigned)__cvta_generic_to_shared(dst);
    asm volatile("cp.async.cg.shared.global [%0], [%1], 16;\n" :: "r"(a), "l"(src));
}
__device__ __forceinline__ void ldm4(unsigned* r, const __half* p) {
    unsigned a = (unsigned)__cvta_generic_to_shared(p);
    asm volatile("ldmatrix.sync.aligned.m8n8.x4.shared.b16 {%0,%1,%2,%3}, [%4];\n"
                 : "=r"(r[0]), "=r"(r[1]), "=r"(r[2]), "=r"(r[3]) : "r"(a));
}
__device__ __forceinline__ void mma16816(float* d, const unsigned* a, const unsigned* b) {
    asm volatile("mma.sync.aligned.m16n8k16.row.col.f32.f16.f16.f32 "
                 "{%0,%1,%2,%3}, {%4,%5,%6,%7}, {%8,%9}, {%0,%1,%2,%3};\n"
                 : "+f"(d[0]), "+f"(d[1]), "+f"(d[2]), "+f"(d[3])
                 : "r"(a[0]), "r"(a[1]), "r"(a[2]), "r"(a[3]), "r"(b[0]), "r"(b[1]));
}
template<int KB>
__device__ __forceinline__ int swz(int row, int chunk) {
    if (KB == 32) return row * 32 + ((chunk ^ ((row >> 1) & 3)) << 3);
    else          return row * 64 + ((chunk ^ (row & 7)) << 3);
}

template<int LA, int TERMS, int KB>
__device__ __forceinline__ void load_stage(__half* dst,
        const __half* Ah, const __half* Al,
        const __half* Bh, const __half* Bl,
        int i0, int j0, int kc, int bwA, int bwB, int t) {
    const int MSZT = 128 * KB;
    const int B_HI = (TERMS == 3) ? 2 * MSZT : MSZT;
    const int NC = KB / 8;                 // 16B chunks per row
    #pragma unroll
    for (int q = 0; q < NC; q++) {
        int idx = t + q * 128;
        int row = idx / NC, c = idx % NC;  // NC power-of-2 -> shifts
        int so = swz<KB>(row, c);
        int ra = i0 + row;
        int ba = ra / LA, la = ra - ba * LA;
        size_t goA = (size_t)ba * bwA + la * 600 + kc + c * 8;
        size_t goB = (size_t)(j0 + row) * bwB + kc + c * 8;
        cp16(dst + so, Ah + goA);
        if (TERMS == 3) cp16(dst + MSZT + so, Al + goA);
        cp16(dst + B_HI + so, Bh + goB);
        if (TERMS >= 2) cp16(dst + B_HI + MSZT + so, Bl + goB);
    }
}

template<int LA, int TERMS, int KB>
__device__ __forceinline__ void gemm_core(
        const __half* Ah, const __half* Al,
        const __half* Bh, const __half* Bl,
        int i0, int j0, int bwA, int bwB, int kIters,
        __half* sm, int t, float acc[4][8][4]) {
    const int MSZT  = 128 * KB;
    const int STG_T = (TERMS + 1) * MSZT;
    const int B_HI  = (TERMS == 3) ? 2 * MSZT : MSZT;
    int lane = t & 31, wid = t >> 5;
    int wm = wid & 1, wn = wid >> 1;
    int lr = lane & 15, lc = (lane >> 4) << 3;

    #pragma unroll
    for (int s = 0; s < GSTAGES - 1; s++) {
        if (s < kIters) load_stage<LA, TERMS, KB>(sm + s * STG_T, Ah, Al, Bh, Bl, i0, j0, s * KB, bwA, bwB, t);
        asm volatile("cp.async.commit_group;\n");
    }
    for (int it = 0; it < kIters; it++) {
        asm volatile("cp.async.wait_group %0;\n" :: "n"(GSTAGES - 2));
        __syncthreads();
        int nxt = it + GSTAGES - 1;
        if (nxt < kIters) load_stage<LA, TERMS, KB>(sm + (nxt % GSTAGES) * STG_T, Ah, Al, Bh, Bl, i0, j0, nxt * KB, bwA, bwB, t);
        asm volatile("cp.async.commit_group;\n");

        const __half* buf = sm + (it % GSTAGES) * STG_T;
        const __half* sAh = buf;
        const __half* sAl = buf + MSZT;
        const __half* sBh = buf + B_HI;
        const __half* sBl = buf + B_HI + MSZT;

        #pragma unroll
        for (int ks = 0; ks < KB; ks += 16) {
            unsigned ah[4][4], al[4][4], bh[8][2], bl[8][2];
            int cl = (ks + lc) >> 3;
            #pragma unroll
            for (int mt = 0; mt < 4; mt++) {
                int rA = wm * 64 + mt * 16 + lr;
                ldm4(ah[mt], sAh + swz<KB>(rA, cl));
                if (TERMS == 3) ldm4(al[mt], sAl + swz<KB>(rA, cl));
            }
            #pragma unroll
            for (int bt = 0; bt < 4; bt++) {
                int rB = wn * 64 + bt * 16 + lr;
                unsigned r4[4];
                ldm4(r4, sBh + swz<KB>(rB, cl));
                bh[2 * bt][0] = r4[0]; bh[2 * bt][1] = r4[2];
                bh[2 * bt + 1][0] = r4[1]; bh[2 * bt + 1][1] = r4[3];
                if (TERMS >= 2) {
                    ldm4(r4, sBl + swz<KB>(rB, cl));
                    bl[2 * bt][0] = r4[0]; bl[2 * bt][1] = r4[2];
                    bl[2 * bt + 1][0] = r4[1]; bl[2 * bt + 1][1] = r4[3];
                }
            }
            #pragma unroll
            for (int mt = 0; mt < 4; mt++)
                #pragma unroll
                for (int nt = 0; nt < 8; nt++) {
                    mma16816(acc[mt][nt], ah[mt], bh[nt]);
                    if (TERMS >= 2) mma16816(acc[mt][nt], ah[mt], bl[nt]);
                    if (TERMS == 3) mma16816(acc[mt][nt], al[mt], bh[nt]);
                }
        }
    }
    __syncthreads();
}

// ---------------- symmetric Gram, triu-packed output ----------------
template<int TERMS, int KB>
__global__ __launch_bounds__(128, 2)
void k_gram_t(const __half* __restrict__ Xhi, const __half* __restrict__ Xlo,
              int ldk, int kIters, float* __restrict__ out) {
    extern __shared__ __half sm[];
    int p = blockIdx.x;
    int ti = 0, rem = 32;
    while (p >= rem) { p -= rem; rem--; ti++; }
    int tj = ti + p;
    const int i0 = ti * GBM, j0 = tj * GBM;

    int t = threadIdx.x;
    float acc[4][8][4];
    #pragma unroll
    for (int mt = 0; mt < 4; mt++)
        #pragma unroll
        for (int nt = 0; nt < 8; nt++)
            #pragma unroll
            for (int e = 0; e < 4; e++) acc[mt][nt][e] = 0.f;

    gemm_core<1, TERMS, KB>(Xhi, Xlo, Xhi, Xlo, i0, j0, ldk, ldk, kIters, sm, t, acc);

    int lane = t & 31, wid = t >> 5;
    int wm = wid & 1, wn = wid >> 1;
    int r = lane >> 2, cp = (lane & 3) * 2;
    #pragma unroll
    for (int mt = 0; mt < 4; mt++) {
        #pragma unroll
        for (int h = 0; h < 2; h++) {
            int i = i0 + wm * 64 + mt * 16 + r + h * 8;
            int base = i * (8191 - i) / 2 - i - 1;
            #pragma unroll
            for (int nt = 0; nt < 8; nt++) {
                int j = j0 + wn * 64 + nt * 8 + cp;
                if (j > i)     out[base + j]     = acc[mt][nt][2 * h + 0];
                if (j + 1 > i) out[base + j + 1] = acc[mt][nt][2 * h + 1];
            }
        }
    }
}

// ---------------- conv GEMM: implicit im2col; MODE 0: bias; MODE 1: bias+tanh ----------------
template<int LA, int MODE, int TERMS, int KB>
__global__ __launch_bounds__(128, 2)
void k_conv_gemm(const __half* __restrict__ Ah, const __half* __restrict__ Al,
                 const __half* __restrict__ Bh, const __half* __restrict__ Bl,
                 int kIters, int bwA, int bwB, int Cout,
                 const float* __restrict__ bias, float* __restrict__ dst, float* __restrict__ out2) {
    extern __shared__ __half sm[];
    const int n0 = blockIdx.x * GBM, m0 = blockIdx.y * GBM;

    int t = threadIdx.x;
    float acc[4][8][4];
    #pragma unroll
    for (int mt = 0; mt < 4; mt++)
        #pragma unroll
        for (int nt = 0; nt < 8; nt++)
            #pragma unroll
            for (int e = 0; e < 4; e++) acc[mt][nt][e] = 0.f;

    gemm_core<LA, TERMS, KB>(Ah, Al, Bh, Bl, m0, n0, bwA, bwB, kIters, sm, t, acc);

    int lane = t & 31, wid = t >> 5;
    int wm = wid & 1, wn = wid >> 1;
    int r = lane >> 2, cp = (lane & 3) * 2;
    #pragma unroll
    for (int mt = 0; mt < 4; mt++) {
        #pragma unroll
        for (int h = 0; h < 2; h++) {
            int m = m0 + wm * 64 + mt * 16 + r + h * 8;
            #pragma unroll
            for (int nt = 0; nt < 8; nt++) {
                int n = n0 + wn * 64 + nt * 8 + cp;
                float a0 = acc[mt][nt][2 * h + 0];
                float a1 = acc[mt][nt][2 * h + 1];
                if (MODE == 0) {
                    if (n < Cout)     dst[(size_t)m * Cout + n]     = a0 + bias[n];
                    if (n + 1 < Cout) dst[(size_t)m * Cout + n + 1] = a1 + bias[n + 1];
                } else {
                    if (n < Cout) {
                        float v = tanhf(a0 + bias[n]);
                        dst[(size_t)m * Cout + n] = v;
                        out2[(size_t)m * Cout + n] = v;
                    }
                    if (n + 1 < Cout) {
                        float v = tanhf(a1 + bias[n + 1]);
                        dst[(size_t)m * Cout + n + 1] = v;
                        out2[(size_t)m * Cout + n + 1] = v;
                    }
                }
            }
        }
    }
}

// ---------------- launch ----------------
extern "C" void kernel_launch(void* const* d_in, const int* in_sizes, int n_in,
                              void* d_out, int out_size) {
    const int*   x   = (const int*)  d_in[0];
    const float* emb = (const float*)d_in[1];
    const float* w1  = (const float*)d_in[2];
    const float* b1  = (const float*)d_in[3];
    const float* w2  = (const float*)d_in[4];
    const float* b2  = (const float*)d_in[5];
    const float* w3  = (const float*)d_in[6];
    const float* b3  = (const float*)d_in[7];
    const float* g1  = (const float*)d_in[8];
    const float* be1 = (const float*)d_in[9];
    const float* g2  = (const float*)d_in[10];
    const float* be2 = (const float*)d_in[11];
    float* out = (float*)d_out;

    const int smem1 = GSTAGES * 2 * (128 * 64) * 2;   // TERMS=1, KB=64: 98304
    const int smem3 = GSTAGES * 4 * (128 * 32) * 2;   // TERMS=3, KB=32: 98304
    cudaFuncSetAttribute(k_gram_t<1,64>,          cudaFuncAttributeMaxDynamicSharedMemorySize, smem1);
    cudaFuncSetAttribute(k_gram_t<3,32>,          cudaFuncAttributeMaxDynamicSharedMemorySize, smem3);
    cudaFuncSetAttribute(k_conv_gemm<13,0,1,64>,  cudaFuncAttributeMaxDynamicSharedMemorySize, smem1);
    cudaFuncSetAttribute(k_conv_gemm<5,0,1,64>,   cudaFuncAttributeMaxDynamicSharedMemorySize, smem1);
    cudaFuncSetAttribute(k_conv_gemm<1,1,3,32>,   cudaFuncAttributeMaxDynamicSharedMemorySize, smem3);

    __half *eh, *w1h, *w2h, *w3h, *w3l;
    __half *h1h, *h2h, *h2l, *fh, *fl;
    float *h1p, *h2p, *finp, *m1p, *i1p, *m2p, *i2p;
    cudaGetSymbolAddress((void**)&eh,  g_Eh);
    cudaGetSymbolAddress((void**)&w1h, g_W1h);
    cudaGetSymbolAddress((void**)&w2h, g_W2h);
    cudaGetSymbolAddress((void**)&w3h, g_W3h);
    cudaGetSymbolAddress((void**)&w3l, g_W3l);
    cudaGetSymbolAddress((void**)&h1h, g_h1h);
    cudaGetSymbolAddress((void**)&h2h, g_h2h);
    cudaGetSymbolAddress((void**)&h2l, g_h2l);
    cudaGetSymbolAddress((void**)&fh,  g_Fnh);
    cudaGetSymbolAddress((void**)&fl,  g_Fnl);
    cudaGetSymbolAddress((void**)&h1p, g_h1);
    cudaGetSymbolAddress((void**)&h2p, g_h2);
    cudaGetSymbolAddress((void**)&finp, g_final);
    cudaGetSymbolAddress((void**)&m1p, g_mean1);
    cudaGetSymbolAddress((void**)&i1p, g_istd1);
    cudaGetSymbolAddress((void**)&m2p, g_mean2);
    cudaGetSymbolAddress((void**)&i2p, g_istd2);

    cudaStream_t s2;
    cudaStreamCreateWithFlags(&s2, cudaStreamNonBlocking);
    cudaEvent_t evPrep, evGather, evJoin;
    cudaEventCreateWithFlags(&evPrep,   cudaEventDisableTiming);
    cudaEventCreateWithFlags(&evGather, cudaEventDisableTiming);
    cudaEventCreateWithFlags(&evJoin,   cudaEventDisableTiming);

    // ---- prologue: scales+gather on main; prep_w+padzero concurrently on s2 ----
    cudaEventRecord(evPrep, 0);
    cudaStreamWaitEvent(s2, evPrep, 0);
    k_prep_w<<<1024, 256, 0, s2>>>(w1, w2, w3);
    k_padzero<<<16, 256, 0, s2>>>();
    cudaEventRecord(evPrep, s2);

    k_scales<<<(VOCAB * 32 + 255) / 256, 256>>>(emb);
    k_gather<<<BATCH, 256>>>(x, emb);
    cudaEventRecord(evGather, 0);

    // s2: big input Gram (KB=64) after gather+pads
    cudaStreamWaitEvent(s2, evGather, 0);
    k_gram_t<1,64><<<528, 128, smem1, s2>>>(eh, eh, BW_E, BW_E / 64, out + HOUT);
    cudaEventRecord(evJoin, s2);

    // main: conv chain (needs prep_w + padzero from s2)
    cudaStreamWaitEvent(0, evPrep, 0);
    {
        dim3 g(3, M1 / GBM);
        k_conv_gemm<13,0,1,64><<<g, 128, smem1>>>(eh, eh, w1h, w1h, K1C / 64, BW_E, K1C, C1, b1, h1p, nullptr);
    }
    k_bnstat_p<<<dim3(10, 32), 256>>>(h1p, M1, C1);
    k_bnstat_r<<<2, 256>>>(C1, 1.f / M1, m1p, i1p);
    k_bnapply<<<2048, 256>>>(h1p, h1h, nullptr, m1p, i1p, g1, be1, M1, C1, L1o, 4);

    {
        dim3 g(5, M2 / GBM);
        k_conv_gemm<5,0,1,64><<<g, 128, smem1>>>(h1h, h1h, w2h, w2h, K1C / 64, BW_H1, K1C, C2, b2, h2p, nullptr);
    }
    k_bnstat_p<<<dim3(19, 32), 256>>>(h2p, M2, C2);
    k_bnstat_r<<<3, 256>>>(C2, 1.f / M2, m2p, i2p);
    k_bnapply<<<2048, 256>>>(h2p, h2h, h2l, m2p, i2p, g2, be2, M2, C2, L2o, 8);

    {
        dim3 g(1, BATCH / GBM);
        k_conv_gemm<1,1,3,32><<<g, 128, smem3>>>(h2h, h2l, w3h, w3l, K3 / 32, BW_H2, K3, C3, b3, finp, out);
    }
    k_norm<<<BATCH * 32 / 256, 256>>>();

    // hidden Gram: 3-term, KB=32
    k_gram_t<3,32><<<528, 128, smem3>>>(fh, fl, KPAD_F, KPAD_F / 32, out + HOUT + NPAIRS);

    // ---- join side stream ----
    cudaStreamWaitEvent(0, evJoin, 0);

    cudaEventDestroy(evPrep);
    cudaEventDestroy(evGather);
    cudaEventDestroy(evJoin);
    cudaStreamDestroy(s2);
}